// round 12
// baseline (speedup 1.0000x reference)
#include <cuda_runtime.h>

// Problem constants (fixed by setup_inputs): B=8, N=20, K=5, Q=15, D=1024
#define BB     8
#define NN     20
#define KSUP   5
#define QQ     15
#define DD     1024
#define ROWS   (KSUP + QQ)        // 20 rows per (b,n)
#define NQ     (NN * QQ)          // 300 queries per batch
#define PAIRS_PER_B 150
#define WARPS  16
#define THREADS 512
#define PPBLK  8                  // pairs per block (x2 D-halves = 16 warps)
#define BPB    19                 // blocks per batch (19*8=152 >= 150 pairs)
#define GRID   (BB * BPB)         // 152 blocks == GB300 SM count, single wave

// Scratch (device globals — no allocation allowed)
__device__ float g_proto[BB * NN * DD];   // 640 KB, L2-resident
__device__ float g_termp[BB * NN];

// ---------------------------------------------------------------------------
// K1: proto[b,n,:] = mean_j support, term_p[b,n] = proto . w0  (computed ONCE)
// ---------------------------------------------------------------------------
__global__ __launch_bounds__(256) void proto_kernel(
    const float* __restrict__ emb, const float* __restrict__ weight)
{
    int bn = blockIdx.x;             // b*20 + n
    int t  = threadIdx.x;            // float4 index 0..255
    const float4* base = reinterpret_cast<const float4*>(emb) + (size_t)bn * ROWS * 256;

    float4 s = base[t];
#pragma unroll
    for (int j = 1; j < KSUP; j++) {
        float4 v = base[j * 256 + t];
        s.x += v.x; s.y += v.y; s.z += v.z; s.w += v.w;
    }
    s.x *= 0.2f; s.y *= 0.2f; s.z *= 0.2f; s.w *= 0.2f;
    reinterpret_cast<float4*>(g_proto)[(size_t)bn * 256 + t] = s;

    float4 w0 = reinterpret_cast<const float4*>(weight)[t];
    float tp = s.x * w0.x + s.y * w0.y + s.z * w0.z + s.w * w0.w;
#pragma unroll
    for (int off = 16; off; off >>= 1) tp += __shfl_xor_sync(0xFFFFFFFFu, tp, off);

    __shared__ float red[8];
    if ((t & 31) == 0) red[t >> 5] = tp;
    __syncthreads();
    if (t == 0) {
        float r = 0.f;
#pragma unroll
        for (int w = 0; w < 8; w++) r += red[w];
        g_termp[bn] = r;
    }
}

// ---------------------------------------------------------------------------
// Main: 152 blocks (= SM count) x 512 threads, one batch per block, single
// wave. Warp = (query-pair, D-half): each LDS.128 of proto feeds 24 FMA ops
// (both queries) — halves smem-crossbar traffic vs R11 (which co-saturated
// with the FFMA pipe) — WITH double-buffered LDS prefetch over i-batches.
// ~124 live regs at the 128 cap. D-half partials combined exactly via smem.
// ---------------------------------------------------------------------------
__global__ __launch_bounds__(THREADS, 1) void relnet_kernel(
    const float* __restrict__ emb,
    const float* __restrict__ weight,
    const float* __restrict__ bias,
    float* __restrict__ out)
{
    extern __shared__ float smem[];
    float4* sP4   = reinterpret_cast<float4*>(smem);               // 20*256 f4 = 81920 B
    float4* sW2   = reinterpret_cast<float4*>(smem + NN * DD);     // 256 f4    =  4096 B
    float*  sTp   = smem + NN * DD + 1024;                         // 20 floats (+12 pad)
    float*  sPart = smem + NN * DD + 1024 + 32;                    // 16*40 floats

    const int tid  = threadIdx.x;
    const int lane = tid & 31;
    const int warp = tid >> 5;
    const int half = warp & 1;                  // D-half owned by this warp
    const int pl   = warp >> 1;                 // local pair 0..7

    const int b      = blockIdx.x / BPB;        // batch
    const int blkInB = blockIdx.x - b * BPB;    // 0..18
    const int pidx   = blkInB * PPBLK + pl;     // pair idx in batch, 0..151
    const bool active = (pidx < PAIRS_PER_B);
    const int q0   = pidx * 2;
    const int q1   = q0 + 1;

    const float4* emb4 = reinterpret_cast<const float4*>(emb);
    const float4* w14  = reinterpret_cast<const float4*>(weight) + 1 * 256;
    const float4* w24  = reinterpret_cast<const float4*>(weight) + 2 * 256;
    const float4* w34  = reinterpret_cast<const float4*>(weight) + 3 * 256;
    const float4* gP4  = reinterpret_cast<const float4*>(g_proto);
    const float bi = bias[0];

    // ---- fill: proto tile for THIS batch, w2, termp ----
#pragma unroll
    for (int k = 0; k < 10; k++) {
        const int idx = k * THREADS + tid;
        sP4[idx] = gP4[(size_t)b * NN * 256 + idx];
    }
    if (tid < 256) sW2[tid] = w24[tid];
    if (tid < NN)  sTp[tid] = g_termp[b * NN + tid];
    __syncthreads();

    if (active) {
        // ---- per-warp regs: both queries' D-half (q, q*w3); tq halves ----
        const int r0row = (b * NN + q0 / QQ) * ROWS + KSUP + q0 % QQ;
        const int r1row = (b * NN + q1 / QQ) * ROWS + KSUP + q1 % QQ;
        const float4* r0 = emb4 + (size_t)r0row * 256 + half * 128;
        const float4* r1 = emb4 + (size_t)r1row * 256 + half * 128;

        float qv0[16], cv0[16], qv1[16], cv1[16];
        float tq0 = 0.f, tq1 = 0.f;
#pragma unroll
        for (int i = 0; i < 4; i++) {
            const int idx = i * 32 + lane;
            float4 a  = r0[idx];
            float4 c  = r1[idx];
            float4 w3 = w34[half * 128 + idx];
            float4 w1 = w14[half * 128 + idx];
            qv0[4*i+0] = a.x; qv0[4*i+1] = a.y; qv0[4*i+2] = a.z; qv0[4*i+3] = a.w;
            qv1[4*i+0] = c.x; qv1[4*i+1] = c.y; qv1[4*i+2] = c.z; qv1[4*i+3] = c.w;
            cv0[4*i+0] = a.x * w3.x; cv0[4*i+1] = a.y * w3.y;
            cv0[4*i+2] = a.z * w3.z; cv0[4*i+3] = a.w * w3.w;
            cv1[4*i+0] = c.x * w3.x; cv1[4*i+1] = c.y * w3.y;
            cv1[4*i+2] = c.z * w3.z; cv1[4*i+3] = c.w * w3.w;
            tq0 = fmaf(a.x, w1.x, tq0); tq0 = fmaf(a.y, w1.y, tq0);
            tq0 = fmaf(a.z, w1.z, tq0); tq0 = fmaf(a.w, w1.w, tq0);
            tq1 = fmaf(c.x, w1.x, tq1); tq1 = fmaf(c.y, w1.y, tq1);
            tq1 = fmaf(c.z, w1.z, tq1); tq1 = fmaf(c.w, w1.w, tq1);
        }
#pragma unroll
        for (int off = 16; off; off >>= 1) {
            tq0 += __shfl_xor_sync(0xFFFFFFFFu, tq0, off);
            tq1 += __shfl_xor_sync(0xFFFFFFFFu, tq1, off);
        }

        // ---- hot loop: 5 n-blocks of 4, double-buffered prefetch over i ----
#pragma unroll 1
        for (int nb = 0; nb < 5; nb++) {
            const float4* pb = sP4 + nb * 4 * 256 + half * 128 + lane;

            float a0[4] = {0.f, 0.f, 0.f, 0.f};
            float a1[4] = {0.f, 0.f, 0.f, 0.f};
            float4 pc[4], w2c;
            w2c = sW2[half * 128 + lane];
#pragma unroll
            for (int n = 0; n < 4; n++) pc[n] = pb[n * 256];

#pragma unroll
            for (int i = 0; i < 4; i++) {
                float4 pn[4], w2n;
                if (i < 3) {                   // prefetch i-batch i+1
                    w2n = sW2[half * 128 + (i + 1) * 32 + lane];
#pragma unroll
                    for (int n = 0; n < 4; n++) pn[n] = pb[n * 256 + (i + 1) * 32];
                }
#pragma unroll
                for (int n = 0; n < 4; n++) {
                    const float4 p = pc[n];
                    a0[n] = fmaf(fabsf(p.x - qv0[4*i+0]), w2c.x, a0[n]);
                    a0[n] = fmaf(p.x, cv0[4*i+0], a0[n]);
                    a1[n] = fmaf(fabsf(p.x - qv1[4*i+0]), w2c.x, a1[n]);
                    a1[n] = fmaf(p.x, cv1[4*i+0], a1[n]);
                    a0[n] = fmaf(fabsf(p.y - qv0[4*i+1]), w2c.y, a0[n]);
                    a0[n] = fmaf(p.y, cv0[4*i+1], a0[n]);
                    a1[n] = fmaf(fabsf(p.y - qv1[4*i+1]), w2c.y, a1[n]);
                    a1[n] = fmaf(p.y, cv1[4*i+1], a1[n]);
                    a0[n] = fmaf(fabsf(p.z - qv0[4*i+2]), w2c.z, a0[n]);
                    a0[n] = fmaf(p.z, cv0[4*i+2], a0[n]);
                    a1[n] = fmaf(fabsf(p.z - qv1[4*i+2]), w2c.z, a1[n]);
                    a1[n] = fmaf(p.z, cv1[4*i+2], a1[n]);
                    a0[n] = fmaf(fabsf(p.w - qv0[4*i+3]), w2c.w, a0[n]);
                    a0[n] = fmaf(p.w, cv0[4*i+3], a0[n]);
                    a1[n] = fmaf(fabsf(p.w - qv1[4*i+3]), w2c.w, a1[n]);
                    a1[n] = fmaf(p.w, cv1[4*i+3], a1[n]);
                }
                if (i < 3) {
#pragma unroll
                    for (int n = 0; n < 4; n++) pc[n] = pn[n];
                    w2c = w2n;
                }
            }

            // deferred reductions: 8 independent butterflies per n-block
#pragma unroll
            for (int n = 0; n < 4; n++) {
                float s0 = a0[n], s1 = a1[n];
#pragma unroll
                for (int off = 16; off; off >>= 1) {
                    s0 += __shfl_xor_sync(0xFFFFFFFFu, s0, off);
                    s1 += __shfl_xor_sync(0xFFFFFFFFu, s1, off);
                }
                if (lane == 0) {
                    const int nn = nb * 4 + n;
                    const float extra = (half == 0) ? sTp[nn] + bi : 0.f;
                    sPart[warp * 40 + nn]      = s0 + tq0 + extra;
                    sPart[warp * 40 + 20 + nn] = s1 + tq1 + extra;
                }
            }
        }
    }

    // ---- combine D-halves: out[q, n] = part[half0] + part[half1] ----
    __syncthreads();
    if (tid < PPBLK * 2 * NN) {               // 320 outputs
        const int ql = tid / NN;              // local query 0..15
        const int n  = tid - ql * NN;
        const int pp = ql >> 1;               // local pair
        const int wh = ql & 1;                // which query of the pair
        const int pi = blkInB * PPBLK + pp;
        if (pi < PAIRS_PER_B) {
            const float v = sPart[(pp * 2 + 0) * 40 + wh * 20 + n]
                          + sPart[(pp * 2 + 1) * 40 + wh * 20 + n];
            out[((size_t)b * NQ + pi * 2 + wh) * NN + n] = v;
        }
    }
}

// ---------------------------------------------------------------------------
// Launch
// ---------------------------------------------------------------------------
static const int SMEM_BYTES = (NN * DD + 1024 + 32 + WARPS * 40) * (int)sizeof(float); // 88,704 B

extern "C" void kernel_launch(void* const* d_in, const int* in_sizes, int n_in,
                              void* d_out, int out_size)
{
    const float* emb    = (const float*)d_in[0];
    const float* weight = (const float*)d_in[1];
    const float* bias   = (const float*)d_in[2];
    float* out          = (float*)d_out;

    cudaFuncSetAttribute(relnet_kernel,
                         cudaFuncAttributeMaxDynamicSharedMemorySize, SMEM_BYTES);

    proto_kernel<<<BB * NN, 256>>>(emb, weight);
    relnet_kernel<<<GRID, THREADS, SMEM_BYTES>>>(emb, weight, bias, out);
}

// round 13
// speedup vs baseline: 1.1113x; 1.1113x over previous
#include <cuda_runtime.h>

// Problem constants (fixed by setup_inputs): B=8, N=20, K=5, Q=15, D=1024
#define BB     8
#define NN     20
#define KSUP   5
#define QQ     15
#define DD     1024
#define ROWS   (KSUP + QQ)        // 20 rows per (b,n)
#define NQ     (NN * QQ)          // 300 queries per batch
#define WARPS  16
#define THREADS 512
#define BPB    19                 // blocks per batch (19*16=304 >= 300 queries)
#define GRID   (BB * BPB)         // 152 blocks == GB300 SM count, single wave

// Scratch (device globals — no allocation allowed)
__device__ float g_proto[BB * NN * DD];   // 640 KB, L2-resident
__device__ float g_termp[BB * NN];

// ---------------------------------------------------------------------------
// K1: proto[b,n,:] = mean_j support, term_p[b,n] = proto . w0  (computed ONCE)
// ---------------------------------------------------------------------------
__global__ __launch_bounds__(256) void proto_kernel(
    const float* __restrict__ emb, const float* __restrict__ weight)
{
    int bn = blockIdx.x;             // b*20 + n
    int t  = threadIdx.x;            // float4 index 0..255
    const float4* base = reinterpret_cast<const float4*>(emb) + (size_t)bn * ROWS * 256;

    float4 s = base[t];
#pragma unroll
    for (int j = 1; j < KSUP; j++) {
        float4 v = base[j * 256 + t];
        s.x += v.x; s.y += v.y; s.z += v.z; s.w += v.w;
    }
    s.x *= 0.2f; s.y *= 0.2f; s.z *= 0.2f; s.w *= 0.2f;
    reinterpret_cast<float4*>(g_proto)[(size_t)bn * 256 + t] = s;

    float4 w0 = reinterpret_cast<const float4*>(weight)[t];
    float tp = s.x * w0.x + s.y * w0.y + s.z * w0.z + s.w * w0.w;
#pragma unroll
    for (int off = 16; off; off >>= 1) tp += __shfl_xor_sync(0xFFFFFFFFu, tp, off);

    __shared__ float red[8];
    if ((t & 31) == 0) red[t >> 5] = tp;
    __syncthreads();
    if (t == 0) {
        float r = 0.f;
#pragma unroll
        for (int w = 0; w < 8; w++) r += red[w];
        g_termp[bn] = r;
    }
}

// ---------------------------------------------------------------------------
// Main: 152 blocks (= SM count) x 512 threads, one batch per block, single
// wave. One query per warp (full D in regs). R11 hot loop, plus:
//  - query LDGs issued BEFORE the smem fill (latency hidden under fill+bar)
//  - cross-nb LDS prefetch (no per-nb-block head stall)
//  - NO shfl reductions: lane-partials stored via issue-only STS into a 40KB
//    smem buffer; one barrier; 320 threads do sequential deterministic sums.
// ---------------------------------------------------------------------------
__global__ __launch_bounds__(THREADS, 1) void relnet_kernel(
    const float* __restrict__ emb,
    const float* __restrict__ weight,
    const float* __restrict__ bias,
    float* __restrict__ out)
{
    extern __shared__ float smem[];
    float4* sP4  = reinterpret_cast<float4*>(smem);                // 20480 f = 81920 B
    float4* sW2  = reinterpret_cast<float4*>(smem + NN * DD);      // 1024 f  =  4096 B
    float*  sTp  = smem + NN * DD + 1024;                          // 20 f (+12 pad)
    float*  sTq  = smem + NN * DD + 1024 + 32;                     // 16 f
    float*  sAcc = smem + NN * DD + 1024 + 32 + 16;                // 16*20*32 f = 40960 B

    const int tid  = threadIdx.x;
    const int lane = tid & 31;
    const int warp = tid >> 5;

    const int b      = blockIdx.x / BPB;          // batch
    const int blkInB = blockIdx.x - b * BPB;      // 0..18
    const int q      = blkInB * WARPS + warp;     // 0..303
    const bool active = (q < NQ);
    const int qc     = active ? q : (NQ - 1);     // clamped for safe addressing

    const float4* emb4 = reinterpret_cast<const float4*>(emb);
    const float4* w14  = reinterpret_cast<const float4*>(weight) + 1 * 256;
    const float4* w24  = reinterpret_cast<const float4*>(weight) + 2 * 256;
    const float4* w34  = reinterpret_cast<const float4*>(weight) + 3 * 256;
    const float4* gP4  = reinterpret_cast<const float4*>(g_proto);
    const float bi = bias[0];

    // ---- issue query/weight LDGs FIRST (latency overlaps the fill below) ----
    const int qrow = (b * NN + qc / QQ) * ROWS + KSUP + qc % QQ;
    const float4* r = emb4 + (size_t)qrow * 256;

    float4 av[8], w3v[8], w1v[8];
#pragma unroll
    for (int i = 0; i < 8; i++) {
        const int idx = i * 32 + lane;
        av[i]  = r[idx];
        w3v[i] = w34[idx];
        w1v[i] = w14[idx];
    }

    // ---- fill: proto tile for THIS batch, w2, termp ----
#pragma unroll
    for (int k = 0; k < 10; k++) {
        const int idx = k * THREADS + tid;
        sP4[idx] = gP4[(size_t)b * NN * 256 + idx];
    }
    if (tid < 256) sW2[tid] = w24[tid];
    if (tid < NN)  sTp[tid] = g_termp[b * NN + tid];

    // ---- derive qv / cv / tq from the prolog loads (regs only) ----
    float qv[32], cv[32];
    float tq = 0.f;
#pragma unroll
    for (int i = 0; i < 8; i++) {
        const float4 a  = av[i];
        const float4 w3 = w3v[i];
        const float4 w1 = w1v[i];
        qv[4*i+0] = a.x; qv[4*i+1] = a.y; qv[4*i+2] = a.z; qv[4*i+3] = a.w;
        cv[4*i+0] = a.x * w3.x; cv[4*i+1] = a.y * w3.y;
        cv[4*i+2] = a.z * w3.z; cv[4*i+3] = a.w * w3.w;
        tq = fmaf(a.x, w1.x, tq); tq = fmaf(a.y, w1.y, tq);
        tq = fmaf(a.z, w1.z, tq); tq = fmaf(a.w, w1.w, tq);
    }
#pragma unroll
    for (int off = 16; off; off >>= 1) tq += __shfl_xor_sync(0xFFFFFFFFu, tq, off);
    if (lane == 0) sTq[warp] = tq;

    __syncthreads();

    if (active) {
        // ---- hot loop: 5 n-blocks of 4, LDS prefetch including across nb ----
        const float4* pb = sP4 + lane;            // + nb*1024 + n*256 + i*32

        float4 pc[4], pn[4], w2c, w2n;
        w2c = sW2[lane];
#pragma unroll
        for (int n = 0; n < 4; n++) pc[n] = pb[n * 256];

#pragma unroll 1
        for (int nb = 0; nb < 5; nb++) {
            float acc[4] = {0.f, 0.f, 0.f, 0.f};

#pragma unroll
            for (int i = 0; i < 8; i++) {
                const bool pf = (i < 7) || (nb < 4);
                if (pf) {
                    const float4* nbase;
                    if (i < 7) {
                        w2n = sW2[(i + 1) * 32 + lane];
                        nbase = pb + nb * 1024 + (i + 1) * 32;
                    } else {
                        w2n = sW2[lane];
                        nbase = pb + (nb + 1) * 1024;
                    }
#pragma unroll
                    for (int n = 0; n < 4; n++) pn[n] = nbase[n * 256];
                }
#pragma unroll
                for (int n = 0; n < 4; n++) {
                    const float4 p = pc[n];
                    acc[n] = fmaf(fabsf(p.x - qv[4*i+0]), w2c.x, acc[n]);
                    acc[n] = fmaf(p.x, cv[4*i+0], acc[n]);
                    acc[n] = fmaf(fabsf(p.y - qv[4*i+1]), w2c.y, acc[n]);
                    acc[n] = fmaf(p.y, cv[4*i+1], acc[n]);
                    acc[n] = fmaf(fabsf(p.z - qv[4*i+2]), w2c.z, acc[n]);
                    acc[n] = fmaf(p.z, cv[4*i+2], acc[n]);
                    acc[n] = fmaf(fabsf(p.w - qv[4*i+3]), w2c.w, acc[n]);
                    acc[n] = fmaf(p.w, cv[4*i+3], acc[n]);
                }
                if (pf) {
#pragma unroll
                    for (int n = 0; n < 4; n++) pc[n] = pn[n];
                    w2c = w2n;
                }
            }

            // issue-only STS of lane partials (no reduction chain, no stall)
#pragma unroll
            for (int n = 0; n < 4; n++)
                sAcc[((warp * NN) + (nb * 4 + n)) * 32 + lane] = acc[n];
        }
    }

    // ---- final combine: 320 threads, sequential deterministic lane sums ----
    __syncthreads();
    if (tid < WARPS * NN) {
        const int w = tid / NN;
        const int n = tid - w * NN;
        const int qq = blkInB * WARPS + w;
        if (qq < NQ) {
            const float4* a = reinterpret_cast<const float4*>(&sAcc[(w * NN + n) * 32]);
            float s = 0.f;
#pragma unroll
            for (int k = 0; k < 8; k++) {
                const float4 v = a[k];
                s += v.x + v.y + v.z + v.w;
            }
            out[((size_t)b * NQ + qq) * NN + n] = s + sTp[n] + sTq[w] + bi;
        }
    }
}

// ---------------------------------------------------------------------------
// Launch
// ---------------------------------------------------------------------------
static const int SMEM_BYTES =
    (NN * DD + 1024 + 32 + 16 + WARPS * NN * 32) * (int)sizeof(float);  // 127,168 B

extern "C" void kernel_launch(void* const* d_in, const int* in_sizes, int n_in,
                              void* d_out, int out_size)
{
    const float* emb    = (const float*)d_in[0];
    const float* weight = (const float*)d_in[1];
    const float* bias   = (const float*)d_in[2];
    float* out          = (float*)d_out;

    cudaFuncSetAttribute(relnet_kernel,
                         cudaFuncAttributeMaxDynamicSharedMemorySize, SMEM_BYTES);

    proto_kernel<<<BB * NN, 256>>>(emb, weight);
    relnet_kernel<<<GRID, THREADS, SMEM_BYTES>>>(emb, weight, bias, out);
}

// round 14
// speedup vs baseline: 1.1196x; 1.0075x over previous
#include <cuda_runtime.h>

// Problem constants (fixed by setup_inputs): B=8, N=20, K=5, Q=15, D=1024
#define BB     8
#define NN     20
#define KSUP   5
#define QQ     15
#define DD     1024
#define ROWS   (KSUP + QQ)        // 20 rows per (b,n)
#define NQ     (NN * QQ)          // 300 queries per batch
#define WARPS  16
#define THREADS 512
#define BPB    19                 // blocks per batch (19*16=304 >= 300 queries)
#define GRID   (BB * BPB)         // 152 blocks == GB300 SM count, single wave

// Scratch (device globals — no allocation allowed)
__device__ float g_proto[BB * NN * DD];   // 640 KB, L2-resident

// ---------------------------------------------------------------------------
// K1 (slim): proto[b,n,:] = mean_j support. No reductions, no smem, no bar.
// 320 blocks = (b,n) x D-half, 128 threads (one float4 each, 5 loads, MLP=5).
// Triggers PDL completion so relnet can start its prolog under our tail.
// ---------------------------------------------------------------------------
__global__ __launch_bounds__(128) void proto_kernel(const float* __restrict__ emb)
{
    const int bn   = blockIdx.x >> 1;
    const int half = blockIdx.x & 1;
    const int t    = threadIdx.x;             // f4 index within half
    const float4* base = reinterpret_cast<const float4*>(emb)
                       + (size_t)bn * ROWS * 256 + half * 128 + t;
    float4 s = base[0];
#pragma unroll
    for (int j = 1; j < KSUP; j++) {
        const float4 v = base[j * 256];
        s.x += v.x; s.y += v.y; s.z += v.z; s.w += v.w;
    }
    s.x *= 0.2f; s.y *= 0.2f; s.z *= 0.2f; s.w *= 0.2f;
    reinterpret_cast<float4*>(g_proto)[(size_t)bn * 256 + half * 128 + t] = s;

    cudaTriggerProgrammaticLaunchCompletion();
}

// ---------------------------------------------------------------------------
// Main: 152 blocks (= SM count) x 512 threads, one batch per block, single
// wave. R11 hot loop unchanged. PDL: query/weight LDGs + w2 smem fill are
// issued BEFORE cudaGridDependencySynchronize(); g_proto is touched only
// after. term_p computed in-block from the smem proto tile (20 warp dots).
// ---------------------------------------------------------------------------
__global__ __launch_bounds__(THREADS, 1) void relnet_kernel(
    const float* __restrict__ emb,
    const float* __restrict__ weight,
    const float* __restrict__ bias,
    float* __restrict__ out)
{
    extern __shared__ float smem[];
    float4* sP4 = reinterpret_cast<float4*>(smem);               // 20*256 f4 = 81920 B
    float4* sW2 = reinterpret_cast<float4*>(smem + NN * DD);     // 256 f4    =  4096 B
    float*  sTp = smem + NN * DD + 1024;                         // 20 floats

    const int tid  = threadIdx.x;
    const int lane = tid & 31;
    const int warp = tid >> 5;

    const int b      = blockIdx.x / BPB;          // batch
    const int blkInB = blockIdx.x - b * BPB;      // 0..18
    const int q      = blkInB * WARPS + warp;     // 0..303
    const bool active = (q < NQ);
    const int qc     = active ? q : (NQ - 1);     // clamped for safe addressing

    const float4* emb4 = reinterpret_cast<const float4*>(emb);
    const float4* w04  = reinterpret_cast<const float4*>(weight);
    const float4* w14  = w04 + 1 * 256;
    const float4* w24  = w04 + 2 * 256;
    const float4* w34  = w04 + 3 * 256;
    const float4* gP4  = reinterpret_cast<const float4*>(g_proto);
    const float bi = bias[0];

    // ---- PDL prolog: LDGs that do NOT depend on g_proto, issued early ----
    const int qrow = (b * NN + qc / QQ) * ROWS + KSUP + qc % QQ;
    const float4* r = emb4 + (size_t)qrow * 256;

    float4 av[8], w3v[8], w1v[8];
#pragma unroll
    for (int i = 0; i < 8; i++) {
        const int idx = i * 32 + lane;
        av[i]  = r[idx];
        w3v[i] = w34[idx];
        w1v[i] = w14[idx];
    }
    if (tid < 256) sW2[tid] = w24[tid];

    // derive qv / cv / tq (regs only, still before the dependency sync)
    float qv[32], cv[32];
    float tq = 0.f;
#pragma unroll
    for (int i = 0; i < 8; i++) {
        const float4 a  = av[i];
        const float4 w3 = w3v[i];
        const float4 w1 = w1v[i];
        qv[4*i+0] = a.x; qv[4*i+1] = a.y; qv[4*i+2] = a.z; qv[4*i+3] = a.w;
        cv[4*i+0] = a.x * w3.x; cv[4*i+1] = a.y * w3.y;
        cv[4*i+2] = a.z * w3.z; cv[4*i+3] = a.w * w3.w;
        tq = fmaf(a.x, w1.x, tq); tq = fmaf(a.y, w1.y, tq);
        tq = fmaf(a.z, w1.z, tq); tq = fmaf(a.w, w1.w, tq);
    }
#pragma unroll
    for (int off = 16; off; off >>= 1) tq += __shfl_xor_sync(0xFFFFFFFFu, tq, off);

    // ---- wait for proto, then fill the smem proto tile ----
    cudaGridDependencySynchronize();
#pragma unroll
    for (int k = 0; k < 10; k++) {
        const int idx = k * THREADS + tid;
        sP4[idx] = gP4[(size_t)b * NN * 256 + idx];
    }
    __syncthreads();

    // ---- term_p in-block: 20 warp dot-products over the smem tile ----
#pragma unroll 1
    for (int n = warp; n < NN; n += WARPS) {
        const float4* pr = sP4 + n * 256;
        float tp = 0.f;
#pragma unroll
        for (int i = 0; i < 8; i++) {
            const int idx = i * 32 + lane;
            const float4 p  = pr[idx];
            const float4 w0 = __ldg(w04 + idx);
            tp = fmaf(p.x, w0.x, tp); tp = fmaf(p.y, w0.y, tp);
            tp = fmaf(p.z, w0.z, tp); tp = fmaf(p.w, w0.w, tp);
        }
#pragma unroll
        for (int off = 16; off; off >>= 1) tp += __shfl_xor_sync(0xFFFFFFFFu, tp, off);
        if (lane == 0) sTp[n] = tp;
    }
    __syncthreads();

    if (!active) return;

    float* o = out + ((size_t)b * NQ + q) * NN;

    // ---- R11 hot loop: 5 n-blocks of 4, double-buffered LDS prefetch ----
#pragma unroll 1
    for (int nb = 0; nb < 5; nb++) {
        const float4* pb = sP4 + nb * 4 * 256 + lane;

        float acc[4] = {0.f, 0.f, 0.f, 0.f};
        float4 pc[4], w2c;
        w2c = sW2[lane];
#pragma unroll
        for (int n = 0; n < 4; n++) pc[n] = pb[n * 256];

#pragma unroll
        for (int i = 0; i < 8; i++) {
            float4 pn[4], w2n;
            if (i < 7) {                       // prefetch batch i+1
                w2n = sW2[(i + 1) * 32 + lane];
#pragma unroll
                for (int n = 0; n < 4; n++) pn[n] = pb[n * 256 + (i + 1) * 32];
            }
#pragma unroll
            for (int n = 0; n < 4; n++) {
                const float4 p = pc[n];
                acc[n] = fmaf(fabsf(p.x - qv[4*i+0]), w2c.x, acc[n]);
                acc[n] = fmaf(p.x, cv[4*i+0], acc[n]);
                acc[n] = fmaf(fabsf(p.y - qv[4*i+1]), w2c.y, acc[n]);
                acc[n] = fmaf(p.y, cv[4*i+1], acc[n]);
                acc[n] = fmaf(fabsf(p.z - qv[4*i+2]), w2c.z, acc[n]);
                acc[n] = fmaf(p.z, cv[4*i+2], acc[n]);
                acc[n] = fmaf(fabsf(p.w - qv[4*i+3]), w2c.w, acc[n]);
                acc[n] = fmaf(p.w, cv[4*i+3], acc[n]);
            }
            if (i < 7) {
#pragma unroll
                for (int n = 0; n < 4; n++) pc[n] = pn[n];
                w2c = w2n;
            }
        }

        // deferred reductions: 4 independent butterflies per n-block
#pragma unroll
        for (int n = 0; n < 4; n++) {
            float s = acc[n];
#pragma unroll
            for (int off = 16; off; off >>= 1)
                s += __shfl_xor_sync(0xFFFFFFFFu, s, off);
            acc[n] = s;
        }
        if (lane == 0) {
#pragma unroll
            for (int n = 0; n < 4; n++) {
                const int nn = nb * 4 + n;
                o[nn] = acc[n] + sTp[nn] + tq + bi;
            }
        }
    }
}

// ---------------------------------------------------------------------------
// Launch: proto (slim) then relnet with PDL (programmatic stream
// serialization) so relnet's prolog overlaps proto's tail.
// ---------------------------------------------------------------------------
static const int SMEM_BYTES = (NN * DD + 1024 + 32) * (int)sizeof(float); // 86,144 B

extern "C" void kernel_launch(void* const* d_in, const int* in_sizes, int n_in,
                              void* d_out, int out_size)
{
    const float* emb    = (const float*)d_in[0];
    const float* weight = (const float*)d_in[1];
    const float* bias   = (const float*)d_in[2];
    float* out          = (float*)d_out;

    cudaFuncSetAttribute(relnet_kernel,
                         cudaFuncAttributeMaxDynamicSharedMemorySize, SMEM_BYTES);

    proto_kernel<<<BB * NN * 2, 128>>>(emb);

    cudaLaunchAttribute attrs[1];
    attrs[0].id = cudaLaunchAttributeProgrammaticStreamSerialization;
    attrs[0].val.programmaticStreamSerializationAllowed = 1;

    cudaLaunchConfig_t cfg = {};
    cfg.gridDim  = dim3(GRID, 1, 1);
    cfg.blockDim = dim3(THREADS, 1, 1);
    cfg.dynamicSmemBytes = SMEM_BYTES;
    cfg.stream = 0;
    cfg.attrs = attrs;
    cfg.numAttrs = 1;
    cudaLaunchKernelEx(&cfg, relnet_kernel, emb, weight, bias, out);
}